// round 14
// baseline (speedup 1.0000x reference)
#include <cuda_runtime.h>
#include <cuda_bf16.h>
#include <cstdint>

#define T_DIM 32
#define WAY 64
#define SHOT 8
#define QUERY 16
#define C_DIM 1024
#define WQ (WAY * QUERY)   // 1024

#define BM 128
#define BK 64
#define NK (C_DIM / BK)    // 16
#define LDS_Q 72           // padded stride (bf16): 36 banks -> conflict-free frags
#define LDS_P 72
#define NTHREADS 512

// Scratch (no allocations allowed): proto bf16 (4 MB) + ||p||^2 fp32.
__device__ __nv_bfloat16 g_proto[T_DIM * WAY * C_DIM];
__device__ float g_psq[T_DIM * WAY];

// ---------------------------------------------------------------------------
// Kernel 1: prototypes (mean over shots) -> bf16, and p_sq (fp32 means)
// grid (WAY, T), 256 threads; each thread owns 4 contiguous columns.
// ---------------------------------------------------------------------------
__global__ __launch_bounds__(256) void proto_kernel(const float* __restrict__ support) {
    const int way = blockIdx.x;
    const int t   = blockIdx.y;
    const int tid = threadIdx.x;

    const float* base = support + ((size_t)t * WAY * SHOT + (size_t)way * SHOT) * C_DIM + tid * 4;

    float4 s = make_float4(0.f, 0.f, 0.f, 0.f);
#pragma unroll
    for (int sh = 0; sh < SHOT; sh++) {
        float4 v = *(const float4*)(base + (size_t)sh * C_DIM);
        s.x += v.x; s.y += v.y; s.z += v.z; s.w += v.w;
    }
    s.x *= 0.125f; s.y *= 0.125f; s.z *= 0.125f; s.w *= 0.125f;

    __nv_bfloat162 lo = __floats2bfloat162_rn(s.x, s.y);
    __nv_bfloat162 hi = __floats2bfloat162_rn(s.z, s.w);
    uint2 packed;
    packed.x = *(const uint32_t*)&lo;
    packed.y = *(const uint32_t*)&hi;
    *(uint2*)&g_proto[((size_t)(t * WAY + way)) * C_DIM + tid * 4] = packed;

    float ss = s.x * s.x + s.y * s.y + s.z * s.z + s.w * s.w;
#pragma unroll
    for (int off = 16; off > 0; off >>= 1)
        ss += __shfl_xor_sync(0xffffffffu, ss, off);

    __shared__ float red[8];
    if ((tid & 31) == 0) red[tid >> 5] = ss;
    __syncthreads();
    if (tid == 0) {
        float tot = 0.f;
#pragma unroll
        for (int w = 0; w < 8; w++) tot += red[w];
        g_psq[t * WAY + way] = tot;
    }
}

// ---------------------------------------------------------------------------
// mma.sync m16n8k16 bf16 -> f32
// ---------------------------------------------------------------------------
__device__ __forceinline__ void mma16816(float* d, const uint32_t* a, const uint32_t* b) {
    asm volatile(
        "mma.sync.aligned.m16n8k16.row.col.f32.bf16.bf16.f32 "
        "{%0,%1,%2,%3}, {%4,%5,%6,%7}, {%8,%9}, {%0,%1,%2,%3};\n"
        : "+f"(d[0]), "+f"(d[1]), "+f"(d[2]), "+f"(d[3])
        : "r"(a[0]), "r"(a[1]), "r"(a[2]), "r"(a[3]), "r"(b[0]), "r"(b[1]));
}

// ---------------------------------------------------------------------------
// Kernel 2: fused GEMM + norms + epilogue. R3 dataflow, 512 threads/CTA.
// grid (8, T). 16 warps (4 M-strips x 4 N-strips of 32x16).
// dist = 2*qp - q_sq - p_sq
// ---------------------------------------------------------------------------
__global__ __launch_bounds__(NTHREADS, 2) void dist_kernel(const float* __restrict__ query,
                                                           float* __restrict__ out) {
    const int t    = blockIdx.y;
    const int rb   = blockIdx.x;
    const int tid  = threadIdx.x;
    const int lane = tid & 31;
    const int warp = tid >> 5;
    const int warpM = warp & 3;   // 0..3 (32-row strips)
    const int warpN = warp >> 2;  // 0..3 (16-col strips)

    __shared__ __align__(16) __nv_bfloat16 sQ[BM * LDS_Q];
    __shared__ __align__(16) __nv_bfloat16 sP[WAY * LDS_P];
    __shared__ float sQsq[BM];
    __shared__ float sPsq[WAY];

    if (tid < WAY) sPsq[tid] = g_psq[t * WAY + tid];

    const float* qbase = query + ((size_t)t * WQ + (size_t)rb * BM) * C_DIM;
    const __nv_bfloat16* pbase = g_proto + (size_t)t * WAY * C_DIM;

    // Q chunk (128x64 f32): 4 threads/row, 4 float4 each
    const int qrow = tid >> 2;           // 0..127
    const int qcol = (tid & 3) * 16;     // f32 col base within BK
    // P chunk (64x64 bf16): 8 threads/row, 1 uint4 (8 bf16) each
    const int prow = tid >> 3;           // 0..63
    const int pcol = (tid & 7) * 8;      // bf16 col within BK

    const float* qsrc = qbase + (size_t)qrow * C_DIM + qcol;
    const __nv_bfloat16* psrc = pbase + (size_t)prow * C_DIM + pcol;

    float4 qreg[4];
    uint4  preg;
    float  qsq = 0.f;
    float  acc[2][2][4];
#pragma unroll
    for (int mt = 0; mt < 2; mt++)
#pragma unroll
        for (int nt = 0; nt < 2; nt++)
#pragma unroll
            for (int i = 0; i < 4; i++) acc[mt][nt][i] = 0.f;

    // prefetch k-chunk 0
#pragma unroll
    for (int i = 0; i < 4; i++) qreg[i] = *(const float4*)(qsrc + i * 4);
    preg = *(const uint4*)(psrc);

    for (int kk = 0; kk < NK; kk++) {
        // ---- stage registers -> smem (convert Q to bf16, accumulate q^2) ----
#pragma unroll
        for (int i = 0; i < 4; i++) {
            float4 v = qreg[i];
            qsq += v.x * v.x + v.y * v.y + v.z * v.z + v.w * v.w;
            __nv_bfloat162 lo = __floats2bfloat162_rn(v.x, v.y);
            __nv_bfloat162 hi = __floats2bfloat162_rn(v.z, v.w);
            uint2 st;
            st.x = *(const uint32_t*)&lo;
            st.y = *(const uint32_t*)&hi;
            *(uint2*)&sQ[qrow * LDS_Q + qcol + i * 4] = st;
        }
        *(uint4*)&sP[prow * LDS_P + pcol] = preg;
        __syncthreads();

        // ---- prefetch next k-chunk while computing on current smem tile ----
        if (kk < NK - 1) {
            const int k0 = (kk + 1) * BK;
#pragma unroll
            for (int i = 0; i < 4; i++) qreg[i] = *(const float4*)(qsrc + k0 + i * 4);
            preg = *(const uint4*)(psrc + k0);
        }

        // ---- compute: 4 k16 steps, 2 m-tiles x 2 n-tiles of m16n8k16 ----
#pragma unroll
        for (int ks = 0; ks < 4; ks++) {
            const int col = ks * 16 + (lane & 3) * 2;
            uint32_t a[2][4], b[2][2];
#pragma unroll
            for (int mt = 0; mt < 2; mt++) {
                const int rr = warpM * 32 + mt * 16 + (lane >> 2);
                a[mt][0] = *(const uint32_t*)&sQ[rr * LDS_Q + col];
                a[mt][1] = *(const uint32_t*)&sQ[(rr + 8) * LDS_Q + col];
                a[mt][2] = *(const uint32_t*)&sQ[rr * LDS_Q + col + 8];
                a[mt][3] = *(const uint32_t*)&sQ[(rr + 8) * LDS_Q + col + 8];
            }
#pragma unroll
            for (int nt = 0; nt < 2; nt++) {
                const int n = warpN * 16 + nt * 8 + (lane >> 2);
                b[nt][0] = *(const uint32_t*)&sP[n * LDS_P + col];
                b[nt][1] = *(const uint32_t*)&sP[n * LDS_P + col + 8];
            }
#pragma unroll
            for (int mt = 0; mt < 2; mt++)
#pragma unroll
                for (int nt = 0; nt < 2; nt++)
                    mma16816(acc[mt][nt], a[mt], b[nt]);
        }
        __syncthreads();
    }

    // ---- q^2: reduce across the 4 col-chunk threads of each row ----
    {
        float v = qsq;
        v += __shfl_xor_sync(0xffffffffu, v, 1);
        v += __shfl_xor_sync(0xffffffffu, v, 2);
        if ((tid & 3) == 0) sQsq[qrow] = v;
    }
    __syncthreads();

    // ---- epilogue: dist = 2*qp - q_sq - p_sq ----
    float* obase = out + ((size_t)t * WQ + (size_t)rb * BM) * WAY;
#pragma unroll
    for (int mt = 0; mt < 2; mt++) {
        const int r0 = warpM * 32 + mt * 16 + (lane >> 2);
        const float qs0 = sQsq[r0];
        const float qs1 = sQsq[r0 + 8];
#pragma unroll
        for (int nt = 0; nt < 2; nt++) {
            const int c0 = warpN * 16 + nt * 8 + (lane & 3) * 2;
            const float ps0 = sPsq[c0];
            const float ps1 = sPsq[c0 + 1];
            float2 d0, d1;
            d0.x = 2.f * acc[mt][nt][0] - qs0 - ps0;
            d0.y = 2.f * acc[mt][nt][1] - qs0 - ps1;
            d1.x = 2.f * acc[mt][nt][2] - qs1 - ps0;
            d1.y = 2.f * acc[mt][nt][3] - qs1 - ps1;
            *(float2*)(obase + (size_t)r0 * WAY + c0) = d0;
            *(float2*)(obase + (size_t)(r0 + 8) * WAY + c0) = d1;
        }
    }
}

extern "C" void kernel_launch(void* const* d_in, const int* in_sizes, int n_in,
                              void* d_out, int out_size) {
    const float* query   = (const float*)d_in[0];   // [32, 1024, 1024]
    const float* support = (const float*)d_in[1];   // [32, 512, 1024]
    float* out = (float*)d_out;                     // [32, 1024, 64]

    proto_kernel<<<dim3(WAY, T_DIM), 256>>>(support);
    dist_kernel<<<dim3(WQ / BM, T_DIM), NTHREADS>>>(query, out);
}

// round 15
// speedup vs baseline: 1.3226x; 1.3226x over previous
#include <cuda_runtime.h>
#include <cuda_bf16.h>
#include <cstdint>

#define T_DIM 32
#define WAY 64
#define SHOT 8
#define QUERY 16
#define C_DIM 1024
#define WQ (WAY * QUERY)   // 1024

#define BM 128
#define BK 64
#define NK (C_DIM / BK)    // 16
#define LDS_Q 72           // padded stride (bf16): 36 banks -> conflict-free frags
#define QTILE (BM * LDS_Q)          // 9216 bf16
#define PTILE (WAY * LDS_Q)         // 4608 bf16
#define STAGE (QTILE + PTILE)       // 13824 bf16 per stage
#define SMEM_BYTES (2 * STAGE * 2)  // 55296 B dynamic

// Scratch (no allocations allowed): proto bf16 (4 MB) + ||p||^2 fp32.
__device__ __nv_bfloat16 g_proto[T_DIM * WAY * C_DIM];
__device__ float g_psq[T_DIM * WAY];

// ---------------------------------------------------------------------------
// Kernel 1: prototypes (mean over shots) -> bf16, and p_sq (fp32 means)
// ---------------------------------------------------------------------------
__global__ __launch_bounds__(256) void proto_kernel(const float* __restrict__ support) {
    const int way = blockIdx.x;
    const int t   = blockIdx.y;
    const int tid = threadIdx.x;

    const float* base = support + ((size_t)t * WAY * SHOT + (size_t)way * SHOT) * C_DIM + tid * 4;

    float4 s = make_float4(0.f, 0.f, 0.f, 0.f);
#pragma unroll
    for (int sh = 0; sh < SHOT; sh++) {
        float4 v = *(const float4*)(base + (size_t)sh * C_DIM);
        s.x += v.x; s.y += v.y; s.z += v.z; s.w += v.w;
    }
    s.x *= 0.125f; s.y *= 0.125f; s.z *= 0.125f; s.w *= 0.125f;

    __nv_bfloat162 lo = __floats2bfloat162_rn(s.x, s.y);
    __nv_bfloat162 hi = __floats2bfloat162_rn(s.z, s.w);
    uint2 packed;
    packed.x = *(const uint32_t*)&lo;
    packed.y = *(const uint32_t*)&hi;
    *(uint2*)&g_proto[((size_t)(t * WAY + way)) * C_DIM + tid * 4] = packed;

    float ss = s.x * s.x + s.y * s.y + s.z * s.z + s.w * s.w;
#pragma unroll
    for (int off = 16; off > 0; off >>= 1)
        ss += __shfl_xor_sync(0xffffffffu, ss, off);

    __shared__ float red[8];
    if ((tid & 31) == 0) red[tid >> 5] = ss;
    __syncthreads();
    if (tid == 0) {
        float tot = 0.f;
#pragma unroll
        for (int w = 0; w < 8; w++) tot += red[w];
        g_psq[t * WAY + way] = tot;
    }
}

// ---------------------------------------------------------------------------
// mma.sync m16n8k16 bf16 -> f32
// ---------------------------------------------------------------------------
__device__ __forceinline__ void mma16816(float* d, const uint32_t* a, const uint32_t* b) {
    asm volatile(
        "mma.sync.aligned.m16n8k16.row.col.f32.bf16.bf16.f32 "
        "{%0,%1,%2,%3}, {%4,%5,%6,%7}, {%8,%9}, {%0,%1,%2,%3};\n"
        : "+f"(d[0]), "+f"(d[1]), "+f"(d[2]), "+f"(d[3])
        : "r"(a[0]), "r"(a[1]), "r"(a[2]), "r"(a[3]), "r"(b[0]), "r"(b[1]));
}

// ---------------------------------------------------------------------------
// Kernel 2: R3 dataflow + double-buffered smem, ONE sync per chunk.
// grid (8, T), 256 threads = 8 warps (4 M-strips x 2 N-strips of 32x32).
// Iter kk: store regs(chunk kk+1)->stage alt, LDG chunk kk+2 -> regs,
//          compute chunk kk from stage cur, sync, flip.
// dist = 2*qp - q_sq - p_sq
// ---------------------------------------------------------------------------
__global__ __launch_bounds__(256, 2) void dist_kernel(const float* __restrict__ query,
                                                      float* __restrict__ out) {
    extern __shared__ __align__(16) __nv_bfloat16 smem[];
    __shared__ float sQsq[BM];
    __shared__ float sPsq[WAY];

    const int t    = blockIdx.y;
    const int rb   = blockIdx.x;
    const int tid  = threadIdx.x;
    const int lane = tid & 31;
    const int warp = tid >> 5;
    const int warpM = warp & 3;   // 0..3 (32-row strips)
    const int warpN = warp >> 2;  // 0..1 (32-col strips)

    if (tid < WAY) sPsq[tid] = g_psq[t * WAY + tid];

    const float* qbase = query + ((size_t)t * WQ + (size_t)rb * BM) * C_DIM;
    const __nv_bfloat16* pbase = g_proto + (size_t)t * WAY * C_DIM;

    // Q tile load mapping: 16 threads per row, float4 each; 16 rows/pass, 8 passes
    const int rg = tid >> 4;            // 0..15
    const int cc = (tid & 15) * 4;      // f32 col within BK
    // P tile load mapping: 4 threads per row, 16 bf16 each
    const int prow = tid >> 2;          // 0..63
    const int pcol = (tid & 3) * 16;    // bf16 col within BK

    float4 qreg[8];
    uint4  preg[2];
    float  qsq[8];
    float  acc[2][4][4];
#pragma unroll
    for (int p = 0; p < 8; p++) qsq[p] = 0.f;
#pragma unroll
    for (int mt = 0; mt < 2; mt++)
#pragma unroll
        for (int nt = 0; nt < 4; nt++)
#pragma unroll
            for (int i = 0; i < 4; i++) acc[mt][nt][i] = 0.f;

    // ---- prologue: chunk 0 -> regs -> stage 0 (+q^2); chunk 1 -> regs ----
#pragma unroll
    for (int p = 0; p < 8; p++)
        qreg[p] = *(const float4*)(qbase + (size_t)(p * 16 + rg) * C_DIM + cc);
    preg[0] = *(const uint4*)(pbase + (size_t)prow * C_DIM + pcol);
    preg[1] = *(const uint4*)(pbase + (size_t)prow * C_DIM + pcol + 8);

    {
        __nv_bfloat16* sQ = smem;
        __nv_bfloat16* sP = smem + QTILE;
#pragma unroll
        for (int p = 0; p < 8; p++) {
            float4 v = qreg[p];
            qsq[p] += v.x * v.x + v.y * v.y + v.z * v.z + v.w * v.w;
            __nv_bfloat162 lo = __floats2bfloat162_rn(v.x, v.y);
            __nv_bfloat162 hi = __floats2bfloat162_rn(v.z, v.w);
            uint2 st;
            st.x = *(const uint32_t*)&lo;
            st.y = *(const uint32_t*)&hi;
            *(uint2*)&sQ[(p * 16 + rg) * LDS_Q + cc] = st;
        }
        *(uint4*)&sP[prow * LDS_Q + pcol] = preg[0];
        *(uint4*)&sP[prow * LDS_Q + pcol + 8] = preg[1];
    }
#pragma unroll
    for (int p = 0; p < 8; p++)
        qreg[p] = *(const float4*)(qbase + (size_t)(p * 16 + rg) * C_DIM + BK + cc);
    preg[0] = *(const uint4*)(pbase + (size_t)prow * C_DIM + BK + pcol);
    preg[1] = *(const uint4*)(pbase + (size_t)prow * C_DIM + BK + pcol + 8);
    __syncthreads();

    for (int kk = 0; kk < NK; kk++) {
        const int cur = kk & 1;
        // ---- store chunk kk+1 (in regs) into the alternate stage ----
        if (kk + 1 < NK) {
            __nv_bfloat16* sQa = smem + (cur ^ 1) * STAGE;
            __nv_bfloat16* sPa = sQa + QTILE;
#pragma unroll
            for (int p = 0; p < 8; p++) {
                float4 v = qreg[p];
                qsq[p] += v.x * v.x + v.y * v.y + v.z * v.z + v.w * v.w;
                __nv_bfloat162 lo = __floats2bfloat162_rn(v.x, v.y);
                __nv_bfloat162 hi = __floats2bfloat162_rn(v.z, v.w);
                uint2 st;
                st.x = *(const uint32_t*)&lo;
                st.y = *(const uint32_t*)&hi;
                *(uint2*)&sQa[(p * 16 + rg) * LDS_Q + cc] = st;
            }
            *(uint4*)&sPa[prow * LDS_Q + pcol] = preg[0];
            *(uint4*)&sPa[prow * LDS_Q + pcol + 8] = preg[1];
        }
        // ---- prefetch chunk kk+2 into regs (full iteration of cover) ----
        if (kk + 2 < NK) {
            const int k0 = (kk + 2) * BK;
#pragma unroll
            for (int p = 0; p < 8; p++)
                qreg[p] = *(const float4*)(qbase + (size_t)(p * 16 + rg) * C_DIM + k0 + cc);
            preg[0] = *(const uint4*)(pbase + (size_t)prow * C_DIM + k0 + pcol);
            preg[1] = *(const uint4*)(pbase + (size_t)prow * C_DIM + k0 + pcol + 8);
        }

        // ---- compute chunk kk from stage cur: 4 k16 steps ----
        const __nv_bfloat16* Qs = smem + cur * STAGE;
        const __nv_bfloat16* Ps = Qs + QTILE;
#pragma unroll
        for (int ks = 0; ks < 4; ks++) {
            const int col = ks * 16 + (lane & 3) * 2;
            uint32_t a[2][4], b[4][2];
#pragma unroll
            for (int mt = 0; mt < 2; mt++) {
                const int rr = warpM * 32 + mt * 16 + (lane >> 2);
                a[mt][0] = *(const uint32_t*)&Qs[rr * LDS_Q + col];
                a[mt][1] = *(const uint32_t*)&Qs[(rr + 8) * LDS_Q + col];
                a[mt][2] = *(const uint32_t*)&Qs[rr * LDS_Q + col + 8];
                a[mt][3] = *(const uint32_t*)&Qs[(rr + 8) * LDS_Q + col + 8];
            }
#pragma unroll
            for (int nt = 0; nt < 4; nt++) {
                const int n = warpN * 32 + nt * 8 + (lane >> 2);
                b[nt][0] = *(const uint32_t*)&Ps[n * LDS_Q + col];
                b[nt][1] = *(const uint32_t*)&Ps[n * LDS_Q + col + 8];
            }
#pragma unroll
            for (int mt = 0; mt < 2; mt++)
#pragma unroll
                for (int nt = 0; nt < 4; nt++)
                    mma16816(acc[mt][nt], a[mt], b[nt]);
        }
        __syncthreads();
    }

    // ---- q^2: reduce across the 16 column-chunk threads of each row ----
#pragma unroll
    for (int p = 0; p < 8; p++) {
        float v = qsq[p];
        v += __shfl_xor_sync(0xffffffffu, v, 1);
        v += __shfl_xor_sync(0xffffffffu, v, 2);
        v += __shfl_xor_sync(0xffffffffu, v, 4);
        v += __shfl_xor_sync(0xffffffffu, v, 8);
        if ((tid & 15) == 0) sQsq[p * 16 + rg] = v;
    }
    __syncthreads();

    // ---- epilogue: dist = 2*qp - q_sq - p_sq ----
    float* obase = out + ((size_t)t * WQ + (size_t)rb * BM) * WAY;
#pragma unroll
    for (int mt = 0; mt < 2; mt++) {
        const int r0 = warpM * 32 + mt * 16 + (lane >> 2);
        const float qs0 = sQsq[r0];
        const float qs1 = sQsq[r0 + 8];
#pragma unroll
        for (int nt = 0; nt < 4; nt++) {
            const int c0 = warpN * 32 + nt * 8 + (lane & 3) * 2;
            const float ps0 = sPsq[c0];
            const float ps1 = sPsq[c0 + 1];
            float2 d0, d1;
            d0.x = 2.f * acc[mt][nt][0] - qs0 - ps0;
            d0.y = 2.f * acc[mt][nt][1] - qs0 - ps1;
            d1.x = 2.f * acc[mt][nt][2] - qs1 - ps0;
            d1.y = 2.f * acc[mt][nt][3] - qs1 - ps1;
            *(float2*)(obase + (size_t)r0 * WAY + c0) = d0;
            *(float2*)(obase + (size_t)(r0 + 8) * WAY + c0) = d1;
        }
    }
}

extern "C" void kernel_launch(void* const* d_in, const int* in_sizes, int n_in,
                              void* d_out, int out_size) {
    const float* query   = (const float*)d_in[0];   // [32, 1024, 1024]
    const float* support = (const float*)d_in[1];   // [32, 512, 1024]
    float* out = (float*)d_out;                     // [32, 1024, 64]

    // Opt in to >48KB dynamic smem (idempotent; capture-safe host-side call).
    cudaFuncSetAttribute(dist_kernel, cudaFuncAttributeMaxDynamicSharedMemorySize,
                         SMEM_BYTES);

    proto_kernel<<<dim3(WAY, T_DIM), 256>>>(support);
    dist_kernel<<<dim3(WQ / BM, T_DIM), 256, SMEM_BYTES>>>(query, out);
}